// round 16
// baseline (speedup 1.0000x reference)
#include <cuda_runtime.h>
#include <cuda_fp16.h>
#include <math_constants.h>
#include <cstdint>

// Problem constants
#define Bz     4
#define C_IN   192
#define Nn     4096
#define BN     (Bz * Nn)          // 16384 nodes
#define E_CNT  262144             // edges
#define C_OUT  384
#define K2     (2 * C_IN)         // 384  (combined GEMM K)
#define CAP    64                 // per-node bucket capacity

// ---------------- scratch (static device globals; no allocation) ----------------
__device__ __align__(16) float g_xt[BN * C_IN];        // node-major fp32 x (agg gather)
__device__ __align__(16) __half g_bx_h[BN * C_IN];     // x   node-major fp16
__device__ __align__(16) __half g_bg_h[BN * C_IN];     // agg node-major fp16
__device__ __align__(16) __half g_a_hi[C_OUT * K2];    // A=[Wx|Wg] K-major fp16 hi
__device__ __align__(16) __half g_a_lo[C_OUT * K2];    // A lo (fp16 residual)
__device__ int   g_cnt[BN];
__device__ int   g_bucket[BN * CAP];     // fixed-stride buckets (4 MB)
__device__ int   g_ovsrc[E_CNT];         // overflow spill (exactness guarantee)
__device__ int   g_ovdst[E_CNT];
__device__ int   g_ovcnt;
__device__ int   g_is64;                 // edge dtype flag (1 = int64, 0 = int32)

// ---------------- helpers ----------------
__device__ __forceinline__ uint32_t smem_u32(const void* p) {
    uint32_t a;
    asm("{ .reg .u64 t; cvta.to.shared.u64 t, %1; cvt.u32.u64 %0, t; }" : "=r"(a) : "l"(p));
    return a;
}

__device__ __forceinline__ void ldsm_x4(uint32_t addr, uint32_t& r0, uint32_t& r1,
                                        uint32_t& r2, uint32_t& r3) {
    asm volatile("ldmatrix.sync.aligned.m8n8.x4.shared.b16 {%0,%1,%2,%3}, [%4];"
                 : "=r"(r0), "=r"(r1), "=r"(r2), "=r"(r3) : "r"(addr));
}

__device__ __forceinline__ void mma_f16(float& c0, float& c1, float& c2, float& c3,
                                        uint32_t a0, uint32_t a1, uint32_t a2, uint32_t a3,
                                        uint32_t b0, uint32_t b1) {
    asm volatile(
        "mma.sync.aligned.m16n8k16.row.col.f32.f16.f16.f32 "
        "{%0,%1,%2,%3}, {%4,%5,%6,%7}, {%8,%9}, {%0,%1,%2,%3};"
        : "+f"(c0), "+f"(c1), "+f"(c2), "+f"(c3)
        : "r"(a0), "r"(a1), "r"(a2), "r"(a3), "r"(b0), "r"(b1));
}

__device__ __forceinline__ void cp_async16(uint32_t smem, const void* gptr) {
    asm volatile("cp.async.cg.shared.global [%0], [%1], 16;" :: "r"(smem), "l"(gptr));
}

__device__ __forceinline__ int load_edge(const void* ei, int idx) {
    if (g_is64) return (int)((const long long*)ei)[idx];
    return ((const int*)ei)[idx];
}

__device__ __forceinline__ float4 max4(float4 a, float4 b) {
    float4 r;
    r.x = fmaxf(a.x, b.x); r.y = fmaxf(a.y, b.y);
    r.z = fmaxf(a.z, b.z); r.w = fmaxf(a.w, b.w);
    return r;
}

// pack a float4 into 4 fp16 (uint2)
__device__ __forceinline__ uint2 pack_h4(float4 v) {
    __half2 h01 = __floats2half2_rn(v.x, v.y);
    __half2 h23 = __floats2half2_rn(v.z, v.w);
    uint2 r;
    r.x = *(uint32_t*)&h01;
    r.y = *(uint32_t*)&h23;
    return r;
}

// ---------------- merged prep: probe + zero counts + W deinterleave/split ------
__global__ void prep_kernel(const void* __restrict__ ei, const float* __restrict__ W) {
    int blk = blockIdx.x;
    int t   = threadIdx.x;
    if (blk == 0) {
        if (t == 0) { g_is64 = 1; g_ovcnt = 0; }
        __threadfence();
        const long long* p = (const long long*)ei;
        long long v = p[t];
        if (v < 0 || v >= BN) atomicExch(&g_is64, 0);
    } else if (blk <= 64) {
        g_cnt[(blk - 1) * 256 + t] = 0;
    } else {
        int i = (blk - 65) * 256 + t;            // over C_OUT*K2
        int o = i / K2, k = i % K2;
        float v = (k < C_IN) ? W[o * K2 + 2 * k] : W[o * K2 + 2 * (k - C_IN) + 1];
        __half hi = __float2half_rn(v);
        __half lo = __float2half_rn(v - __half2float(hi));
        g_a_hi[i] = hi;
        g_a_lo[i] = lo;
    }
}

// ---------------- fused transpose + scatter ----------------
// blocks 0..1023    : edge scatter into fixed-capacity buckets
// blocks 1024..4095 : x (B,C,N) -> node-major fp32 + fp16 (32x32 tiles)
__global__ void transpose_scatter_kernel(const float* __restrict__ x,
                                         const void* __restrict__ ei) {
    __shared__ float tile[32][33];
    int blk = blockIdx.x;
    int tid = threadIdx.x;

    if (blk < 1024) {
        int e = blk * 256 + tid;
        int d = load_edge(ei, e);
        int s = load_edge(ei, E_CNT + e);
        if ((unsigned)d < BN && (unsigned)s < BN) {
            int pos = atomicAdd(&g_cnt[d], 1);
            if (pos < CAP) {
                g_bucket[d * CAP + pos] = s;
            } else {                              // exact spill path (≈never)
                int op = atomicAdd(&g_ovcnt, 1);
                if (op < E_CNT) { g_ovsrc[op] = s; g_ovdst[op] = d; }
            }
        }
        return;
    }

    int q  = blk - 1024;                 // 0..3071
    int n0 = (q & 127) * 32;             // 128 n-tiles
    int c0 = ((q >> 7) % 6) * 32;        // 6 c-tiles
    int b  = q / (128 * 6);              // 4 batches
    int tx = tid & 31, ty = tid >> 5;    // 32 x 8
    #pragma unroll
    for (int i = 0; i < 4; ++i) {
        int c = c0 + ty + 8 * i;
        tile[ty + 8 * i][tx] = x[((size_t)b * C_IN + c) * Nn + n0 + tx];
    }
    __syncthreads();
    #pragma unroll
    for (int i = 0; i < 4; ++i) {
        int n = n0 + ty + 8 * i;
        size_t idx = ((size_t)b * Nn + n) * C_IN + c0 + tx;
        float v = tile[tx][ty + 8 * i];
        g_xt[idx] = v;
        g_bx_h[idx] = __float2half_rn(v);
    }
}

// ---------------- aggregation: one warp per node, float4 gathers ----------------
__global__ void agg_kernel() {
    int gtid = blockIdx.x * blockDim.x + threadIdx.x;
    int node = gtid >> 5;
    int lane = threadIdx.x & 31;
    if (node >= BN) return;
    int deg = g_cnt[node];
    int nb  = deg < CAP ? deg : CAP;
    bool lo16 = lane < 16;

    const float4 NEG4 = make_float4(-CUDART_INF_F, -CUDART_INF_F, -CUDART_INF_F, -CUDART_INF_F);
    float4 ma = NEG4, mb = NEG4;

    const int* brow = g_bucket + node * CAP;
    int my_src = (lane < nb) ? brow[lane] : 0;
    int cnt = nb < 32 ? nb : 32;

    int i = 0;
    for (; i + 4 <= cnt; i += 4) {       // 4 neighbors in flight, float4-wide
        int s0 = __shfl_sync(0xFFFFFFFFu, my_src, i);
        int s1 = __shfl_sync(0xFFFFFFFFu, my_src, i + 1);
        int s2 = __shfl_sync(0xFFFFFFFFu, my_src, i + 2);
        int s3 = __shfl_sync(0xFFFFFFFFu, my_src, i + 3);
        const float4* r0 = (const float4*)(g_xt + (size_t)s0 * C_IN);
        const float4* r1 = (const float4*)(g_xt + (size_t)s1 * C_IN);
        const float4* r2 = (const float4*)(g_xt + (size_t)s2 * C_IN);
        const float4* r3 = (const float4*)(g_xt + (size_t)s3 * C_IN);
        float4 a0 = r0[lane], a1 = r1[lane], a2 = r2[lane], a3 = r3[lane];
        if (lo16) {
            float4 b0 = r0[32 + lane], b1 = r1[32 + lane];
            float4 b2 = r2[32 + lane], b3 = r3[32 + lane];
            mb = max4(mb, max4(max4(b0, b1), max4(b2, b3)));
        }
        ma = max4(ma, max4(max4(a0, a1), max4(a2, a3)));
    }
    for (; i < cnt; ++i) {
        int s0 = __shfl_sync(0xFFFFFFFFu, my_src, i);
        const float4* r0 = (const float4*)(g_xt + (size_t)s0 * C_IN);
        ma = max4(ma, r0[lane]);
        if (lo16) mb = max4(mb, r0[32 + lane]);
    }
    for (int e = 32; e < nb; ++e) {
        int s = brow[e];
        const float4* r = (const float4*)(g_xt + (size_t)s * C_IN);
        ma = max4(ma, r[lane]);
        if (lo16) mb = max4(mb, r[32 + lane]);
    }
    int nov = g_ovcnt;
    if (nov > E_CNT) nov = E_CNT;
    for (int e = 0; e < nov; ++e) {
        if (g_ovdst[e] == node) {
            const float4* r = (const float4*)(g_xt + (size_t)g_ovsrc[e] * C_IN);
            ma = max4(ma, r[lane]);
            if (lo16) mb = max4(mb, r[32 + lane]);
        }
    }

    const float4* xr = (const float4*)(g_xt + (size_t)node * C_IN);
    bool has = deg > 0;
    {
        float4 xa = xr[lane];
        float4 va = has ? make_float4(ma.x - xa.x, ma.y - xa.y, ma.z - xa.z, ma.w - xa.w)
                        : make_float4(0.f, 0.f, 0.f, 0.f);
        *(uint2*)((char*)g_bg_h + ((size_t)node * C_IN + lane * 4) * 2) = pack_h4(va);
    }
    if (lo16) {
        float4 xb = xr[32 + lane];
        float4 vb = has ? make_float4(mb.x - xb.x, mb.y - xb.y, mb.z - xb.z, mb.w - xb.w)
                        : make_float4(0.f, 0.f, 0.f, 0.f);
        *(uint2*)((char*)g_bg_h + ((size_t)node * C_IN + 128 + lane * 4) * 2) = pack_h4(vb);
    }
}

// ---------------- HMMA GEMM (double-buffered cp.async): out = relu(A@B + bias) --
// 2-term fp16 split: D = A_hi*B + A_lo*B (fp32 reg accum). Dropped term is
// A*(B - fp16(B)) ~ 2^-11 RMS (measured rel_err 2.1e-4 in R14, 5x under thresh).
// CTA tile 128(M) x 64(N); 8 warps = 4(M) x 2(N), warp tile 32 x 32.
// Grid 768 -> waves 296+296+176 (tail ~16% vs 35% at grid 384).
// 12 K-chunks of 32 fp16. Stage = Ah,Al (128x80B) + Bh (64x80B) = 25600B;
// 2 stages = 51200B dynamic smem. Pitch 80B = 20-bank stride, conflict-free.

#define PITCH_B 80
#define A_ROWS 128
#define B_ROWS 64
#define A_GRANULES (A_ROWS * 4)         // 512 data granules
#define B_GRANULES (B_ROWS * 4)         // 256 data granules
#define OFF_AH 0
#define OFF_AL (A_ROWS * PITCH_B)                   // 10240
#define OFF_BH (2 * A_ROWS * PITCH_B)               // 20480
#define STAGE_BYTES (2 * A_ROWS * PITCH_B + B_ROWS * PITCH_B)  // 25600
#define GEMM_SMEM (2 * STAGE_BYTES)                 // 51200
#define NCHUNK 12

extern __shared__ __align__(16) char g_dsm[];

__global__ __launch_bounds__(256, 2) void hmma_gemm_kernel(
    const float* __restrict__ bias, float* __restrict__ out)
{
    int tid  = threadIdx.x;
    int wid  = tid >> 5;
    int lane = tid & 31;
    int wm   = wid & 3;        // warp row 0..3  -> m offset wm*32
    int wn   = wid >> 2;       // warp col 0..1  -> n offset wn*32
    int n0 = blockIdx.x * 64;
    int m0 = blockIdx.y * 128;
    int bb = blockIdx.z;

    uint32_t dsm = smem_u32(g_dsm);
    int row_in = lane & 7;
    int sub    = lane >> 3;      // 0..3
    int node0  = bb * Nn + n0;

    const char* a_hi = (const char*)g_a_hi;
    const char* a_lo = (const char*)g_a_lo;

    auto load_stage = [&](int stage, int cc) {     // cc = 0..11
        const char* b_src = (cc < 6) ? (const char*)g_bx_h : (const char*)g_bg_h;
        int kkA = cc * 32;                          // A K-offset (fp16 elements)
        int kkB = (cc % 6) * 32;                    // B K-offset within its source
        uint32_t st = dsm + stage * STAGE_BYTES;
        for (int g = tid; g < A_GRANULES; g += 256) {    // 512 data granules
            int row = g >> 2, q = g & 3;
            size_t a_off = (size_t)(m0 + row) * (K2 * 2) + kkA * 2 + q * 16;
            uint32_t so = row * PITCH_B + q * 16;
            cp_async16(st + OFF_AH + so, a_hi + a_off);
            cp_async16(st + OFF_AL + so, a_lo + a_off);
        }
        for (int g = tid; g < B_GRANULES; g += 256) {    // 256 data granules
            int row = g >> 2, q = g & 3;
            size_t b_off = (size_t)(node0 + row) * (C_IN * 2) + kkB * 2 + q * 16;
            uint32_t so = row * PITCH_B + q * 16;
            cp_async16(st + OFF_BH + so, b_src + b_off);
        }
    };

    float acc[2][4][4];
    #pragma unroll
    for (int i = 0; i < 2; ++i)
        #pragma unroll
        for (int j = 0; j < 4; ++j)
            #pragma unroll
            for (int r = 0; r < 4; ++r) acc[i][j][r] = 0.0f;

    load_stage(0, 0);
    asm volatile("cp.async.commit_group;" ::: "memory");

    for (int cc = 0; cc < NCHUNK; ++cc) {
        if (cc < NCHUNK - 1) {
            load_stage((cc + 1) & 1, cc + 1);
            asm volatile("cp.async.commit_group;" ::: "memory");
            asm volatile("cp.async.wait_group 1;" ::: "memory");
        } else {
            asm volatile("cp.async.wait_group 0;" ::: "memory");
        }
        __syncthreads();

        uint32_t st = dsm + (cc & 1) * STAGE_BYTES;
        #pragma unroll
        for (int ks = 0; ks < 2; ++ks) {
            int k0 = ks * 16;
            uint32_t a_row_off  = (wm * 32 + row_in + (sub & 1) * 8) * PITCH_B
                                  + (k0 + (sub >> 1) * 8) * 2;
            uint32_t b_lane_off = (wn * 32 + (sub >> 1) * 8 + row_in) * PITCH_B
                                  + (k0 + (sub & 1) * 8) * 2;

            uint32_t ah[2][4], al[2][4];
            #pragma unroll
            for (int f = 0; f < 2; ++f)
                ldsm_x4(st + OFF_AH + a_row_off + f * 16 * PITCH_B,
                        ah[f][0], ah[f][1], ah[f][2], ah[f][3]);

            uint32_t bf[4][2];
            #pragma unroll
            for (int j = 0; j < 2; ++j) {
                uint32_t r0, r1, r2, r3;
                ldsm_x4(st + OFF_BH + b_lane_off + j * 16 * PITCH_B, r0, r1, r2, r3);
                bf[j * 2][0] = r0; bf[j * 2][1] = r1;
                bf[j * 2 + 1][0] = r2; bf[j * 2 + 1][1] = r3;
            }
            // hi * B
            #pragma unroll
            for (int mi = 0; mi < 2; ++mi)
                #pragma unroll
                for (int nj = 0; nj < 4; ++nj)
                    mma_f16(acc[mi][nj][0], acc[mi][nj][1], acc[mi][nj][2], acc[mi][nj][3],
                            ah[mi][0], ah[mi][1], ah[mi][2], ah[mi][3],
                            bf[nj][0], bf[nj][1]);
            // lo * B
            #pragma unroll
            for (int f = 0; f < 2; ++f)
                ldsm_x4(st + OFF_AL + a_row_off + f * 16 * PITCH_B,
                        al[f][0], al[f][1], al[f][2], al[f][3]);
            #pragma unroll
            for (int mi = 0; mi < 2; ++mi)
                #pragma unroll
                for (int nj = 0; nj < 4; ++nj)
                    mma_f16(acc[mi][nj][0], acc[mi][nj][1], acc[mi][nj][2], acc[mi][nj][3],
                            al[mi][0], al[mi][1], al[mi][2], al[mi][3],
                            bf[nj][0], bf[nj][1]);
        }
        __syncthreads();
    }

    // epilogue: bias + relu
    int g  = lane >> 2;        // 0..7
    int tq = lane & 3;         // 0..3
    #pragma unroll
    for (int mi = 0; mi < 2; ++mi) {
        int r0 = m0 + wm * 32 + mi * 16 + g;
        int r1 = r0 + 8;
        float bv0 = bias[r0];
        float bv1 = bias[r1];
        float* o0 = out + ((size_t)bb * C_OUT + r0) * Nn + n0 + wn * 32 + tq * 2;
        float* o1 = out + ((size_t)bb * C_OUT + r1) * Nn + n0 + wn * 32 + tq * 2;
        #pragma unroll
        for (int nj = 0; nj < 4; ++nj) {
            float2 v0, v1;
            v0.x = fmaxf(acc[mi][nj][0] + bv0, 0.0f);
            v0.y = fmaxf(acc[mi][nj][1] + bv0, 0.0f);
            v1.x = fmaxf(acc[mi][nj][2] + bv1, 0.0f);
            v1.y = fmaxf(acc[mi][nj][3] + bv1, 0.0f);
            *(float2*)(o0 + nj * 8) = v0;
            *(float2*)(o1 + nj * 8) = v1;
        }
    }
}

// ---------------- launcher ----------------
extern "C" void kernel_launch(void* const* d_in, const int* in_sizes, int n_in,
                              void* d_out, int out_size) {
    const float* x  = (const float*)d_in[0];       // (4,192,4096,1)
    const void*  ei = (const void*)d_in[1];        // (2, 262144) int32 or int64
    const float* W  = (const float*)d_in[2];       // (384, 384)
    const float* bv = (const float*)d_in[3];       // (384,)
    float* out = (float*)d_out;                    // (4,384,4096,1)

    cudaFuncSetAttribute(hmma_gemm_kernel,
                         cudaFuncAttributeMaxDynamicSharedMemorySize, GEMM_SMEM);

    prep_kernel<<<641, 256>>>(ei, W);                                   // 1
    transpose_scatter_kernel<<<4096, 256>>>(x, ei);                     // 2
    agg_kernel<<<(BN * 32) / 256, 256>>>();                             // 3
    hmma_gemm_kernel<<<dim3(Nn / 64, C_OUT / 128, Bz), 256, GEMM_SMEM>>>(bv, out); // 4
}

// round 17
// speedup vs baseline: 1.2999x; 1.2999x over previous
#include <cuda_runtime.h>
#include <cuda_fp16.h>
#include <math_constants.h>
#include <cstdint>

// Problem constants
#define Bz     4
#define C_IN   192
#define Nn     4096
#define BN     (Bz * Nn)          // 16384 nodes
#define E_CNT  262144             // edges
#define C_OUT  384
#define K2     (2 * C_IN)         // 384  (combined GEMM K)
#define CAP    64                 // per-node bucket capacity

// ---------------- scratch (static device globals; no allocation) ----------------
__device__ __align__(16) __half g_bx_h[BN * C_IN];     // x   node-major fp16
__device__ __align__(16) __half g_bg_h[BN * C_IN];     // agg node-major fp16
__device__ __align__(16) __half g_a_h[C_OUT * K2];     // A=[Wx|Wg] K-major fp16
__device__ int   g_cnt[BN];
__device__ int   g_bucket[BN * CAP];     // fixed-stride buckets (4 MB)
__device__ int   g_ovsrc[E_CNT];         // overflow spill (exactness guarantee)
__device__ int   g_ovdst[E_CNT];
__device__ int   g_ovcnt;
__device__ int   g_is64;                 // edge dtype flag (1 = int64, 0 = int32)

// ---------------- helpers ----------------
__device__ __forceinline__ uint32_t smem_u32(const void* p) {
    uint32_t a;
    asm("{ .reg .u64 t; cvta.to.shared.u64 t, %1; cvt.u32.u64 %0, t; }" : "=r"(a) : "l"(p));
    return a;
}

__device__ __forceinline__ void ldsm_x4(uint32_t addr, uint32_t& r0, uint32_t& r1,
                                        uint32_t& r2, uint32_t& r3) {
    asm volatile("ldmatrix.sync.aligned.m8n8.x4.shared.b16 {%0,%1,%2,%3}, [%4];"
                 : "=r"(r0), "=r"(r1), "=r"(r2), "=r"(r3) : "r"(addr));
}

__device__ __forceinline__ void mma_f16(float& c0, float& c1, float& c2, float& c3,
                                        uint32_t a0, uint32_t a1, uint32_t a2, uint32_t a3,
                                        uint32_t b0, uint32_t b1) {
    asm volatile(
        "mma.sync.aligned.m16n8k16.row.col.f32.f16.f16.f32 "
        "{%0,%1,%2,%3}, {%4,%5,%6,%7}, {%8,%9}, {%0,%1,%2,%3};"
        : "+f"(c0), "+f"(c1), "+f"(c2), "+f"(c3)
        : "r"(a0), "r"(a1), "r"(a2), "r"(a3), "r"(b0), "r"(b1));
}

__device__ __forceinline__ int load_edge(const void* ei, int idx) {
    if (g_is64) return (int)((const long long*)ei)[idx];
    return ((const int*)ei)[idx];
}

__device__ __forceinline__ uint32_t hmax2u(uint32_t a, uint32_t b) {
    __half2 r = __hmax2(*(__half2*)&a, *(__half2*)&b);
    return *(uint32_t*)&r;
}
__device__ __forceinline__ uint32_t hsub2u(uint32_t a, uint32_t b) {
    __half2 r = __hsub2(*(__half2*)&a, *(__half2*)&b);
    return *(uint32_t*)&r;
}
__device__ __forceinline__ uint4 max4h(uint4 a, uint4 b) {
    uint4 r;
    r.x = hmax2u(a.x, b.x); r.y = hmax2u(a.y, b.y);
    r.z = hmax2u(a.z, b.z); r.w = hmax2u(a.w, b.w);
    return r;
}

// ---------------- merged prep: probe + zero counts + W deinterleave ----------
__global__ void prep_kernel(const void* __restrict__ ei, const float* __restrict__ W) {
    int blk = blockIdx.x;
    int t   = threadIdx.x;
    if (blk == 0) {
        if (t == 0) { g_is64 = 1; g_ovcnt = 0; }
        __threadfence();
        const long long* p = (const long long*)ei;
        long long v = p[t];
        if (v < 0 || v >= BN) atomicExch(&g_is64, 0);
    } else if (blk <= 64) {
        g_cnt[(blk - 1) * 256 + t] = 0;
    } else {
        int i = (blk - 65) * 256 + t;            // over C_OUT*K2
        int o = i / K2, k = i % K2;
        float v = (k < C_IN) ? W[o * K2 + 2 * k] : W[o * K2 + 2 * (k - C_IN) + 1];
        g_a_h[i] = __float2half_rn(v);
    }
}

// ---------------- fused transpose + scatter ----------------
// blocks 0..1023    : edge scatter into fixed-capacity buckets
// blocks 1024..4095 : x (B,C,N) -> node-major fp16 (32x32 tiles)
__global__ void transpose_scatter_kernel(const float* __restrict__ x,
                                         const void* __restrict__ ei) {
    __shared__ float tile[32][33];
    int blk = blockIdx.x;
    int tid = threadIdx.x;

    if (blk < 1024) {
        int e = blk * 256 + tid;
        int d = load_edge(ei, e);
        int s = load_edge(ei, E_CNT + e);
        if ((unsigned)d < BN && (unsigned)s < BN) {
            int pos = atomicAdd(&g_cnt[d], 1);
            if (pos < CAP) {
                g_bucket[d * CAP + pos] = s;
            } else {                              // exact spill path (≈never)
                int op = atomicAdd(&g_ovcnt, 1);
                if (op < E_CNT) { g_ovsrc[op] = s; g_ovdst[op] = d; }
            }
        }
        return;
    }

    int q  = blk - 1024;                 // 0..3071
    int n0 = (q & 127) * 32;             // 128 n-tiles
    int c0 = ((q >> 7) % 6) * 32;        // 6 c-tiles
    int b  = q / (128 * 6);              // 4 batches
    int tx = tid & 31, ty = tid >> 5;    // 32 x 8
    #pragma unroll
    for (int i = 0; i < 4; ++i) {
        int c = c0 + ty + 8 * i;
        tile[ty + 8 * i][tx] = x[((size_t)b * C_IN + c) * Nn + n0 + tx];
    }
    __syncthreads();
    #pragma unroll
    for (int i = 0; i < 4; ++i) {
        int n = n0 + ty + 8 * i;
        size_t idx = ((size_t)b * Nn + n) * C_IN + c0 + tx;
        g_bx_h[idx] = __float2half_rn(tile[tx][ty + 8 * i]);
    }
}

// ---------------- aggregation: one warp per node, fp16 uint4 gathers -----------
// Row = 192 fp16 = 384B = 24 granules of 16B; lanes 0..23 own one granule each
// (8 consecutive channels). Max in packed half2; subtract own row; store fp16.
__global__ void agg_kernel() {
    int gtid = blockIdx.x * blockDim.x + threadIdx.x;
    int node = gtid >> 5;
    int lane = threadIdx.x & 31;
    if (node >= BN) return;
    int deg = g_cnt[node];
    int nb  = deg < CAP ? deg : CAP;
    bool act = lane < 24;

    const __half NEGH = __float2half(-CUDART_INF_F);
    __half2 nh2 = __half2half2(NEGH);
    uint32_t NEGU = *(uint32_t*)&nh2;
    uint4 m = make_uint4(NEGU, NEGU, NEGU, NEGU);

    const int* brow = g_bucket + node * CAP;
    int my_src = (lane < nb) ? brow[lane] : 0;
    int cnt = nb < 32 ? nb : 32;

    int i = 0;
    for (; i + 4 <= cnt; i += 4) {       // 4 neighbors in flight, 16B each
        int s0 = __shfl_sync(0xFFFFFFFFu, my_src, i);
        int s1 = __shfl_sync(0xFFFFFFFFu, my_src, i + 1);
        int s2 = __shfl_sync(0xFFFFFFFFu, my_src, i + 2);
        int s3 = __shfl_sync(0xFFFFFFFFu, my_src, i + 3);
        if (act) {
            const uint4* r0 = (const uint4*)(g_bx_h + (size_t)s0 * C_IN);
            const uint4* r1 = (const uint4*)(g_bx_h + (size_t)s1 * C_IN);
            const uint4* r2 = (const uint4*)(g_bx_h + (size_t)s2 * C_IN);
            const uint4* r3 = (const uint4*)(g_bx_h + (size_t)s3 * C_IN);
            uint4 a0 = r0[lane], a1 = r1[lane], a2 = r2[lane], a3 = r3[lane];
            m = max4h(m, max4h(max4h(a0, a1), max4h(a2, a3)));
        }
    }
    for (; i < cnt; ++i) {
        int s0 = __shfl_sync(0xFFFFFFFFu, my_src, i);
        if (act) {
            const uint4* r0 = (const uint4*)(g_bx_h + (size_t)s0 * C_IN);
            m = max4h(m, r0[lane]);
        }
    }
    for (int e = 32; e < nb; ++e) {      // rare tail (deg in (32, CAP])
        int s = brow[e];
        if (act) {
            const uint4* r = (const uint4*)(g_bx_h + (size_t)s * C_IN);
            m = max4h(m, r[lane]);
        }
    }
    int nov = g_ovcnt;                   // exact overflow sweep (==0 in practice)
    if (nov > E_CNT) nov = E_CNT;
    for (int e = 0; e < nov; ++e) {
        if (g_ovdst[e] == node && act) {
            const uint4* r = (const uint4*)(g_bx_h + (size_t)g_ovsrc[e] * C_IN);
            m = max4h(m, r[lane]);
        }
    }

    if (act) {
        const uint4* xr = (const uint4*)(g_bx_h + (size_t)node * C_IN);
        uint4 xi = xr[lane];
        uint4 v;
        if (deg > 0) {
            v.x = hsub2u(m.x, xi.x); v.y = hsub2u(m.y, xi.y);
            v.z = hsub2u(m.z, xi.z); v.w = hsub2u(m.w, xi.w);
        } else {
            v = make_uint4(0, 0, 0, 0);
        }
        *((uint4*)(g_bg_h + (size_t)node * C_IN) + lane) = v;
    }
}

// ---------------- HMMA GEMM: out = relu(fp16(A) @ fp16(B) + bias) -------------
// Pure fp16 operands, fp32 accumulate. Predicted rel_err ~3e-4 (B-only rounding
// measured 2.1e-4; A adds ~sqrt(2)x). CTA tile 128(M) x 128(N); 8 warps =
// 4(M) x 2(N), warp tile 32 x 64. 6 K-chunks of 64 fp16; 2 smem tiles (A, B)
// = 36864B; __launch_bounds__(256,3) -> 3 CTAs/SM, 24 warps/SM, grid 384 fits
// in ONE wave (384 < 148*3). smem pitch 144B -> conflict-free ldmatrix.

#define PITCH_B 144
#define TILE_BYTES (128 * PITCH_B)     // 18432
#define OFF_A 0
#define OFF_B TILE_BYTES
#define GEMM_SMEM (2 * TILE_BYTES)     // 36864

extern __shared__ __align__(16) char g_dsm[];

__global__ __launch_bounds__(256, 3) void hmma_gemm_kernel(
    const float* __restrict__ bias, float* __restrict__ out)
{
    char* At = g_dsm;
    char* Bt = g_dsm + OFF_B;

    int tid  = threadIdx.x;
    int wid  = tid >> 5;
    int lane = tid & 31;
    int wm   = wid & 3;        // warp row 0..3  -> m offset wm*32
    int wn   = wid >> 2;       // warp col 0..1  -> n offset wn*64
    int n0 = blockIdx.x * 128;
    int m0 = blockIdx.y * 128;
    int bb = blockIdx.z;

    uint32_t a_base = smem_u32(At);
    uint32_t b_base = smem_u32(Bt);

    int row_in = lane & 7;
    int sub    = lane >> 3;      // 0..3

    const char* a_src = (const char*)g_a_h;
    const char* bx_h  = (const char*)g_bx_h;
    const char* bg_h  = (const char*)g_bg_h;

    int node0 = bb * Nn + n0;

    float acc[2][8][4];
    #pragma unroll
    for (int i = 0; i < 2; ++i)
        #pragma unroll
        for (int j = 0; j < 8; ++j)
            #pragma unroll
            for (int r = 0; r < 4; ++r) acc[i][j][r] = 0.0f;

    for (int c6 = 0; c6 < 6; ++c6) {
        const char* b_src = (c6 < 3) ? bx_h : bg_h;
        int kkA = c6 * 64;                 // A K-offset (fp16 elements)
        int kkB = (c6 % 3) * 64;           // B K-offset within its source

        // fill 2 tiles: each thread writes 4 granules per tile
        #pragma unroll
        for (int i = 0; i < 4; ++i) {
            int idx = tid + 256 * i;       // 0..1023
            int row = idx >> 3;
            int q   = idx & 7;
            size_t a_off = (size_t)(m0 + row) * (K2 * 2) + kkA * 2 + q * 16;
            size_t b_off = (size_t)(node0 + row) * (C_IN * 2) + kkB * 2 + q * 16;
            uint32_t so = row * PITCH_B + q * 16;
            *(uint4*)(At + so) = *(const uint4*)(a_src + a_off);
            *(uint4*)(Bt + so) = *(const uint4*)(b_src + b_off);
        }
        __syncthreads();

        #pragma unroll
        for (int ks = 0; ks < 4; ++ks) {
            int k0 = ks * 16;
            uint32_t a_row_off  = (wm * 32 + row_in + (sub & 1) * 8) * PITCH_B
                                  + (k0 + (sub >> 1) * 8) * 2;
            uint32_t b_lane_off = (wn * 64 + (sub >> 1) * 8 + row_in) * PITCH_B
                                  + (k0 + (sub & 1) * 8) * 2;

            uint32_t af[2][4];
            #pragma unroll
            for (int f = 0; f < 2; ++f)
                ldsm_x4(a_base + a_row_off + f * 16 * PITCH_B,
                        af[f][0], af[f][1], af[f][2], af[f][3]);

            uint32_t bh[8][2];
            #pragma unroll
            for (int j = 0; j < 4; ++j) {
                uint32_t r0, r1, r2, r3;
                ldsm_x4(b_base + b_lane_off + j * 16 * PITCH_B, r0, r1, r2, r3);
                bh[j * 2][0] = r0; bh[j * 2][1] = r1;
                bh[j * 2 + 1][0] = r2; bh[j * 2 + 1][1] = r3;
            }
            #pragma unroll
            for (int mi = 0; mi < 2; ++mi)
                #pragma unroll
                for (int nj = 0; nj < 8; ++nj)
                    mma_f16(acc[mi][nj][0], acc[mi][nj][1], acc[mi][nj][2], acc[mi][nj][3],
                            af[mi][0], af[mi][1], af[mi][2], af[mi][3],
                            bh[nj][0], bh[nj][1]);
        }
        __syncthreads();
    }

    // epilogue: bias + relu
    int g  = lane >> 2;        // 0..7
    int tq = lane & 3;         // 0..3
    #pragma unroll
    for (int mi = 0; mi < 2; ++mi) {
        int r0 = m0 + wm * 32 + mi * 16 + g;
        int r1 = r0 + 8;
        float bv0 = bias[r0];
        float bv1 = bias[r1];
        float* o0 = out + ((size_t)bb * C_OUT + r0) * Nn + n0 + wn * 64 + tq * 2;
        float* o1 = out + ((size_t)bb * C_OUT + r1) * Nn + n0 + wn * 64 + tq * 2;
        #pragma unroll
        for (int nj = 0; nj < 8; ++nj) {
            float2 v0, v1;
            v0.x = fmaxf(acc[mi][nj][0] + bv0, 0.0f);
            v0.y = fmaxf(acc[mi][nj][1] + bv0, 0.0f);
            v1.x = fmaxf(acc[mi][nj][2] + bv1, 0.0f);
            v1.y = fmaxf(acc[mi][nj][3] + bv1, 0.0f);
            *(float2*)(o0 + nj * 8) = v0;
            *(float2*)(o1 + nj * 8) = v1;
        }
    }
}

// ---------------- launcher ----------------
extern "C" void kernel_launch(void* const* d_in, const int* in_sizes, int n_in,
                              void* d_out, int out_size) {
    const float* x  = (const float*)d_in[0];       // (4,192,4096,1)
    const void*  ei = (const void*)d_in[1];        // (2, 262144) int32 or int64
    const float* W  = (const float*)d_in[2];       // (384, 384)
    const float* bv = (const float*)d_in[3];       // (384,)
    float* out = (float*)d_out;                    // (4,384,4096,1)

    cudaFuncSetAttribute(hmma_gemm_kernel,
                         cudaFuncAttributeMaxDynamicSharedMemorySize, GEMM_SMEM);

    prep_kernel<<<641, 256>>>(ei, W);                                   // 1
    transpose_scatter_kernel<<<4096, 256>>>(x, ei);                     // 2
    agg_kernel<<<(BN * 32) / 256, 256>>>();                             // 3
    hmma_gemm_kernel<<<dim3(Nn / 128, C_OUT / 128, Bz), 256, GEMM_SMEM>>>(bv, out); // 4
}